// round 13
// baseline (speedup 1.0000x reference)
#include <cuda_runtime.h>
#include <cuda_bf16.h>
#include <cstdint>

#define NODES_MAX 50000
#define EDGES_MAX 800000
#define FIN 256
#define FE  64
#define FTOT 320
#define FOUT 256

// ---------------------------------------------------------------------------
// Scratch (__device__ globals; allocation-free rule)
// ---------------------------------------------------------------------------
__device__ __nv_bfloat16 g_agg_hi[(size_t)NODES_MAX * FTOT];  // 32 MB
__device__ __nv_bfloat16 g_agg_lo[(size_t)NODES_MAX * FTOT];  // 32 MB
__device__ __nv_bfloat16 g_wt_hi[(size_t)FOUT * FTOT];        // W^T [N,K]
__device__ __nv_bfloat16 g_wt_lo[(size_t)FOUT * FTOT];
__device__ int   g_outd[NODES_MAX];
__device__ int   g_ind[NODES_MAX];
__device__ int   g_cursor[NODES_MAX];
__device__ float g_norm_out[NODES_MAX];
__device__ float g_norm_in[NODES_MAX];
__device__ int   g_rowstart[NODES_MAX + 1];
__device__ int   g_bsum[256];
__device__ int2  g_csr[EDGES_MAX];

// ---------------------------------------------------------------------------
__global__ void zero_kernel(int N) {
    int i = blockIdx.x * blockDim.x + threadIdx.x;
    if (i < N) { g_outd[i] = 0; g_ind[i] = 0; g_cursor[i] = 0; }
}

__global__ void deg_kernel(const int* __restrict__ src,
                           const int* __restrict__ dst, int E) {
    int e = blockIdx.x * blockDim.x + threadIdx.x;
    if (e < E) {
        atomicAdd(&g_outd[src[e]], 1);
        atomicAdd(&g_ind[dst[e]], 1);
    }
}

// W [320,256] row-major -> Wt [256,320] bf16 hi/lo
__global__ void wsplit_kernel(const float* __restrict__ W) {
    int idx = blockIdx.x * blockDim.x + threadIdx.x;
    if (idx < FTOT * FOUT) {
        int k = idx >> 8;      // /256
        int n = idx & 255;
        float w = W[idx];
        __nv_bfloat16 h = __float2bfloat16(w);
        __nv_bfloat16 l = __float2bfloat16(w - __bfloat162float(h));
        g_wt_hi[(size_t)n * FTOT + k] = h;
        g_wt_lo[(size_t)n * FTOT + k] = l;
    }
}

// ---- scanA: fused norm computation + exclusive scan of g_ind ----
__global__ void scanA_kernel(int N) {
    __shared__ int sm[512];
    int t = threadIdx.x;
    int i = blockIdx.x * 512 + t;
    int v = 0;
    if (i < N) {
        int od = g_outd[i], id = g_ind[i];
        g_norm_out[i] = rsqrtf((float)max(od, 1));
        g_norm_in[i]  = rsqrtf((float)max(id, 1));
        v = id;
    }
    sm[t] = v;
    __syncthreads();
#pragma unroll
    for (int off = 1; off < 512; off <<= 1) {
        int x = (t >= off) ? sm[t - off] : 0;
        __syncthreads();
        sm[t] += x;
        __syncthreads();
    }
    if (i <= N) g_rowstart[i] = sm[t] - v;
    if (t == 511) g_bsum[blockIdx.x] = sm[511];
}

// parallel block-sum exclusive scan (nblocks <= 128)
__global__ void scanB_kernel(int nblocks) {
    __shared__ int sm[128];
    int t = threadIdx.x;
    int v = (t < nblocks) ? g_bsum[t] : 0;
    sm[t] = v;
    __syncthreads();
#pragma unroll
    for (int off = 1; off < 128; off <<= 1) {
        int x = (t >= off) ? sm[t - off] : 0;
        __syncthreads();
        sm[t] += x;
        __syncthreads();
    }
    if (t < nblocks) g_bsum[t] = sm[t] - v;   // exclusive
}

__global__ void scanC_kernel(int N, int E) {
    int i = blockIdx.x * 512 + threadIdx.x;
    if (i < N) g_rowstart[i] += g_bsum[blockIdx.x];
    if (i == N) g_rowstart[N] = E;
}

__global__ void fill_kernel(const int* __restrict__ src,
                            const int* __restrict__ dst, int E) {
    int e = blockIdx.x * blockDim.x + threadIdx.x;
    if (e < E) {
        int d = dst[e];
        int pos = g_rowstart[d] + atomicAdd(&g_cursor[d], 1);
        g_csr[pos] = make_int2(src[e], e);
    }
}

// ---------------------------------------------------------------------------
// Gather aggregation -> bf16 hi/lo rows of [agg_h | agg_e]
// One 64-lane group per dst node; edge loop unrolled x2 (dual accumulators)
// for memory-level parallelism on the L2-latency-bound feat gather.
// edge_feat loaded evict-first (read-once stream; protect feat in L2).
// ---------------------------------------------------------------------------
__device__ __forceinline__ void split_store2(__nv_bfloat16* hi, __nv_bfloat16* lo,
                                             float a, float b) {
    __nv_bfloat16 ha = __float2bfloat16(a), hb = __float2bfloat16(b);
    __nv_bfloat16 la = __float2bfloat16(a - __bfloat162float(ha));
    __nv_bfloat16 lb = __float2bfloat16(b - __bfloat162float(hb));
    *(__nv_bfloat162*)hi = __nv_bfloat162(ha, hb);
    *(__nv_bfloat162*)lo = __nv_bfloat162(la, lb);
}

__global__ __launch_bounds__(256)
void agg_kernel(const float4* __restrict__ feat4,
                const float4* __restrict__ edge4, int N, int E) {
    int node = blockIdx.x * 4 + (threadIdx.x >> 6);
    int lane = threadIdx.x & 63;
    if (node >= N) return;
    int beg = g_rowstart[node];
    int end = g_rowstart[node + 1];

    float4 acc0 = make_float4(0.f, 0.f, 0.f, 0.f);
    float4 acc1 = make_float4(0.f, 0.f, 0.f, 0.f);
    float4 ae0  = make_float4(0.f, 0.f, 0.f, 0.f);
    float4 ae1  = make_float4(0.f, 0.f, 0.f, 0.f);

    int i = beg;
    if ((end - beg) & 1) {
        int2 e0 = __ldg(&g_csr[i]);
        float n0 = g_norm_out[e0.x];
        float4 v0 = __ldg(feat4 + (size_t)e0.x * (FIN / 4) + lane);
        acc0.x = fmaf(v0.x, n0, acc0.x); acc0.y = fmaf(v0.y, n0, acc0.y);
        acc0.z = fmaf(v0.z, n0, acc0.z); acc0.w = fmaf(v0.w, n0, acc0.w);
        if (lane < FE / 4) {
            float4 ev = __ldcs(edge4 + (size_t)e0.y * (FE / 4) + lane);
            ae0.x += ev.x; ae0.y += ev.y; ae0.z += ev.z; ae0.w += ev.w;
        }
        i++;
    }
    for (; i < end; i += 2) {
        int2 e0 = __ldg(&g_csr[i]);
        int2 e1 = __ldg(&g_csr[i + 1]);
        float n0 = g_norm_out[e0.x];
        float n1 = g_norm_out[e1.x];
        float4 v0 = __ldg(feat4 + (size_t)e0.x * (FIN / 4) + lane);
        float4 v1 = __ldg(feat4 + (size_t)e1.x * (FIN / 4) + lane);
        acc0.x = fmaf(v0.x, n0, acc0.x); acc0.y = fmaf(v0.y, n0, acc0.y);
        acc0.z = fmaf(v0.z, n0, acc0.z); acc0.w = fmaf(v0.w, n0, acc0.w);
        acc1.x = fmaf(v1.x, n1, acc1.x); acc1.y = fmaf(v1.y, n1, acc1.y);
        acc1.z = fmaf(v1.z, n1, acc1.z); acc1.w = fmaf(v1.w, n1, acc1.w);
        if (lane < FE / 4) {
            float4 w0 = __ldcs(edge4 + (size_t)e0.y * (FE / 4) + lane);
            float4 w1 = __ldcs(edge4 + (size_t)e1.y * (FE / 4) + lane);
            ae0.x += w0.x; ae0.y += w0.y; ae0.z += w0.z; ae0.w += w0.w;
            ae1.x += w1.x; ae1.y += w1.y; ae1.z += w1.z; ae1.w += w1.w;
        }
    }
    float4 acc = make_float4(acc0.x + acc1.x, acc0.y + acc1.y,
                             acc0.z + acc1.z, acc0.w + acc1.w);
    float4 acce = make_float4(ae0.x + ae1.x, ae0.y + ae1.y,
                              ae0.z + ae1.z, ae0.w + ae1.w);

    __nv_bfloat16* rh = g_agg_hi + (size_t)node * FTOT;
    __nv_bfloat16* rl = g_agg_lo + (size_t)node * FTOT;
    split_store2(rh + lane * 4,     rl + lane * 4,     acc.x, acc.y);
    split_store2(rh + lane * 4 + 2, rl + lane * 4 + 2, acc.z, acc.w);
    if (lane < FE / 4) {
        split_store2(rh + FIN + lane * 4,     rl + FIN + lane * 4,     acce.x, acce.y);
        split_store2(rh + FIN + lane * 4 + 2, rl + FIN + lane * 4 + 2, acce.z, acce.w);
    }
}

// ---------------------------------------------------------------------------
// Tensor-core GEMM via mma.sync (R8/R11 version, measured best):
//   out[128-tile, 128-tile] = agg(hi,lo) [M,320] @ Wt(hi,lo)^T [256,320]
// CTA: 256 thr = 8 warps (2m x 4n); warp tile 64x32; K-chunks of 32.
// ---------------------------------------------------------------------------
#define KC 32
#define AST 40   // smem row stride (bf16 units): conflict-free frag loads

__device__ __forceinline__ void mma16816(float* c, const uint32_t* a, const uint32_t* b) {
    asm volatile("mma.sync.aligned.m16n8k16.row.col.f32.bf16.bf16.f32 "
        "{%0,%1,%2,%3}, {%4,%5,%6,%7}, {%8,%9}, {%0,%1,%2,%3};"
        : "+f"(c[0]), "+f"(c[1]), "+f"(c[2]), "+f"(c[3])
        : "r"(a[0]), "r"(a[1]), "r"(a[2]), "r"(a[3]), "r"(b[0]), "r"(b[1]));
}

__global__ __launch_bounds__(256)
void gemm_mma_kernel(const float* __restrict__ bias,
                     float* __restrict__ out, int M) {
    __shared__ __nv_bfloat16 Ah[128 * AST], Al[128 * AST];
    __shared__ __nv_bfloat16 Bh[128 * AST], Bl[128 * AST];

    int tid = threadIdx.x;
    int wid = tid >> 5, lid = tid & 31;
    int row0 = blockIdx.y * 128;
    int col0 = blockIdx.x * 128;
    int wm = (wid >> 2) * 64;      // warp m offset: 0/64
    int wn = (wid & 3) * 32;       // warp n offset: 0/32/64/96
    int qr = lid >> 2;             // 0..7
    int qc = (lid & 3) * 2;        // 0,2,4,6

    float acc[4][4][4];
#pragma unroll
    for (int mf = 0; mf < 4; mf++)
#pragma unroll
        for (int nf = 0; nf < 4; nf++)
#pragma unroll
            for (int q = 0; q < 4; q++) acc[mf][nf][q] = 0.f;

    int r_ = tid >> 2, u_ = tid & 3;
    const int NCH = FTOT / KC;   // 10

    uint4 pah[2], pal[2], pbh[2], pbl[2];
    uint4 z4 = make_uint4(0, 0, 0, 0);

#define LOAD_CHUNK(c)                                                          \
    {                                                                          \
        _Pragma("unroll")                                                      \
        for (int i = 0; i < 2; i++) {                                          \
            int r = r_ + i * 64;                                               \
            int rg = row0 + r;                                                 \
            size_t go = (size_t)rg * FTOT + (c) * KC + u_ * 8;                 \
            if (rg < M) {                                                      \
                pah[i] = *(const uint4*)(g_agg_hi + go);                       \
                pal[i] = *(const uint4*)(g_agg_lo + go);                       \
            } else { pah[i] = z4; pal[i] = z4; }                               \
            size_t gw = (size_t)(col0 + r) * FTOT + (c) * KC + u_ * 8;         \
            pbh[i] = *(const uint4*)(g_wt_hi + gw);                            \
            pbl[i] = *(const uint4*)(g_wt_lo + gw);                            \
        }                                                                      \
    }

    LOAD_CHUNK(0);

    for (int c = 0; c < NCH; c++) {
#pragma unroll
        for (int i = 0; i < 2; i++) {
            int r = r_ + i * 64;
            int so = r * AST + u_ * 8;
            *(uint4*)&Ah[so] = pah[i];
            *(uint4*)&Al[so] = pal[i];
            *(uint4*)&Bh[so] = pbh[i];
            *(uint4*)&Bl[so] = pbl[i];
        }
        __syncthreads();

        if (c + 1 < NCH) LOAD_CHUNK(c + 1);

#pragma unroll
        for (int ko = 0; ko < KC; ko += 16) {
            uint32_t bh[4][2], bl[4][2];
#pragma unroll
            for (int nf = 0; nf < 4; nf++) {
                int nrow = wn + nf * 8 + qr;
                bh[nf][0] = *(const uint32_t*)&Bh[nrow * AST + ko + qc];
                bh[nf][1] = *(const uint32_t*)&Bh[nrow * AST + ko + qc + 8];
                bl[nf][0] = *(const uint32_t*)&Bl[nrow * AST + ko + qc];
                bl[nf][1] = *(const uint32_t*)&Bl[nrow * AST + ko + qc + 8];
            }
#pragma unroll
            for (int mf = 0; mf < 4; mf++) {
                int mrow = wm + mf * 16 + qr;
                uint32_t ah[4], al[4];
                ah[0] = *(const uint32_t*)&Ah[mrow * AST + ko + qc];
                ah[1] = *(const uint32_t*)&Ah[(mrow + 8) * AST + ko + qc];
                ah[2] = *(const uint32_t*)&Ah[mrow * AST + ko + qc + 8];
                ah[3] = *(const uint32_t*)&Ah[(mrow + 8) * AST + ko + qc + 8];
                al[0] = *(const uint32_t*)&Al[mrow * AST + ko + qc];
                al[1] = *(const uint32_t*)&Al[(mrow + 8) * AST + ko + qc];
                al[2] = *(const uint32_t*)&Al[mrow * AST + ko + qc + 8];
                al[3] = *(const uint32_t*)&Al[(mrow + 8) * AST + ko + qc + 8];
#pragma unroll
                for (int nf = 0; nf < 4; nf++) {
                    mma16816(acc[mf][nf], ah, bh[nf]);   // Ah*Bh
                    mma16816(acc[mf][nf], ah, bl[nf]);   // Ah*Bl
                    mma16816(acc[mf][nf], al, bh[nf]);   // Al*Bh
                }
            }
        }
        __syncthreads();
    }

#pragma unroll
    for (int mf = 0; mf < 4; mf++) {
        int ra = row0 + wm + mf * 16 + qr;
        int rb = ra + 8;
        float na = (ra < M) ? g_norm_in[ra] : 0.f;
        float nb = (rb < M) ? g_norm_in[rb] : 0.f;
#pragma unroll
        for (int nf = 0; nf < 4; nf++) {
            int col = col0 + wn + nf * 8 + qc;
            float b0 = __ldg(bias + col), b1 = __ldg(bias + col + 1);
            if (ra < M) {
                float2 o;
                o.x = fmaxf(fmaf(acc[mf][nf][0], na, b0), 0.f);
                o.y = fmaxf(fmaf(acc[mf][nf][1], na, b1), 0.f);
                *(float2*)&out[(size_t)ra * FOUT + col] = o;
            }
            if (rb < M) {
                float2 o;
                o.x = fmaxf(fmaf(acc[mf][nf][2], nb, b0), 0.f);
                o.y = fmaxf(fmaf(acc[mf][nf][3], nb, b1), 0.f);
                *(float2*)&out[(size_t)rb * FOUT + col] = o;
            }
        }
    }
}

// ---------------------------------------------------------------------------
extern "C" void kernel_launch(void* const* d_in, const int* in_sizes, int n_in,
                              void* d_out, int out_size) {
    const float* feat      = (const float*)d_in[0];
    const float* edge_feat = (const float*)d_in[1];
    const float* weight    = (const float*)d_in[2];
    const float* bias      = (const float*)d_in[3];
    const int*   src       = (const int*)d_in[4];
    const int*   dst       = (const int*)d_in[5];
    float* out = (float*)d_out;

    int N = in_sizes[0] / FIN;   // 50000
    int E = in_sizes[4];         // 800000

    int scan_blocks = (N + 512) / 512;   // 98

    zero_kernel<<<(N + 255) / 256, 256>>>(N);
    deg_kernel<<<(E + 255) / 256, 256>>>(src, dst, E);
    scanA_kernel<<<scan_blocks, 512>>>(N);      // norms fused here
    scanB_kernel<<<1, 128>>>(scan_blocks);
    scanC_kernel<<<scan_blocks, 512>>>(N, E);
    fill_kernel<<<(E + 255) / 256, 256>>>(src, dst, E);
    wsplit_kernel<<<(FTOT * FOUT + 255) / 256, 256>>>(weight);

    agg_kernel<<<(N + 3) / 4, 256>>>((const float4*)feat, (const float4*)edge_feat, N, E);

    dim3 ggrid(FOUT / 128, (N + 127) / 128);
    gemm_mma_kernel<<<ggrid, 256>>>(bias, out, N);
}

// round 14
// speedup vs baseline: 1.0667x; 1.0667x over previous
#include <cuda_runtime.h>
#include <cuda_bf16.h>
#include <cstdint>

#define NODES_MAX 50000
#define EDGES_MAX 800000
#define FIN 256
#define FE  64
#define FTOT 320
#define FOUT 256

// ---------------------------------------------------------------------------
// Scratch (__device__ globals; allocation-free rule)
// ---------------------------------------------------------------------------
__device__ __nv_bfloat16 g_agg_hi[(size_t)NODES_MAX * FTOT];  // 32 MB
__device__ __nv_bfloat16 g_agg_lo[(size_t)NODES_MAX * FTOT];  // 32 MB
__device__ __nv_bfloat16 g_wt_hi[(size_t)FOUT * FTOT];        // W^T [N,K]
__device__ __nv_bfloat16 g_wt_lo[(size_t)FOUT * FTOT];
__device__ int   g_outd[NODES_MAX];
__device__ int   g_ind[NODES_MAX];
__device__ int   g_cursor[NODES_MAX];
__device__ float g_norm_out[NODES_MAX];
__device__ float g_norm_in[NODES_MAX];
__device__ int   g_rowstart[NODES_MAX + 1];
__device__ int   g_bsum[256];
__device__ int2  g_csr[EDGES_MAX];

// ---------------------------------------------------------------------------
__global__ void zero_kernel(int N) {
    int i = blockIdx.x * blockDim.x + threadIdx.x;
    if (i < N) { g_outd[i] = 0; g_ind[i] = 0; }
}

__global__ void deg_kernel(const int* __restrict__ src,
                           const int* __restrict__ dst, int E) {
    int e = blockIdx.x * blockDim.x + threadIdx.x;
    if (e < E) {
        atomicAdd(&g_outd[src[e]], 1);
        atomicAdd(&g_ind[dst[e]], 1);
    }
}

// W [320,256] row-major -> Wt [256,320] bf16 hi/lo
__global__ void wsplit_kernel(const float* __restrict__ W) {
    int idx = blockIdx.x * blockDim.x + threadIdx.x;
    if (idx < FTOT * FOUT) {
        int k = idx >> 8;      // /256
        int n = idx & 255;
        float w = W[idx];
        __nv_bfloat16 h = __float2bfloat16(w);
        __nv_bfloat16 l = __float2bfloat16(w - __bfloat162float(h));
        g_wt_hi[(size_t)n * FTOT + k] = h;
        g_wt_lo[(size_t)n * FTOT + k] = l;
    }
}

// ---- scanA: fused norm computation + cursor clear + block scan of g_ind ----
__global__ void scanA_kernel(int N) {
    __shared__ int sm[512];
    int t = threadIdx.x;
    int i = blockIdx.x * 512 + t;
    int v = 0;
    if (i < N) {
        int od = g_outd[i], id = g_ind[i];
        g_norm_out[i] = rsqrtf((float)max(od, 1));
        g_norm_in[i]  = rsqrtf((float)max(id, 1));
        g_cursor[i] = 0;
        v = id;
    }
    sm[t] = v;
    __syncthreads();
#pragma unroll
    for (int off = 1; off < 512; off <<= 1) {
        int x = (t >= off) ? sm[t - off] : 0;
        __syncthreads();
        sm[t] += x;
        __syncthreads();
    }
    if (i <= N) g_rowstart[i] = sm[t] - v;   // exclusive (within block)
    if (t == 511) g_bsum[blockIdx.x] = sm[511];
}

// scanC: each block reduces g_bsum[0..bid) locally (removes scanB launch)
__global__ void scanC_kernel(int N, int E, int nblocks) {
    __shared__ int warpsum[4];
    __shared__ int s_off;
    int t = threadIdx.x;
    int bid = blockIdx.x;
    if (t < 128) {
        int v = (t < nblocks && t < bid) ? g_bsum[t] : 0;
#pragma unroll
        for (int o = 16; o > 0; o >>= 1) v += __shfl_down_sync(0xffffffffu, v, o);
        if ((t & 31) == 0) warpsum[t >> 5] = v;
    }
    __syncthreads();
    if (t == 0) s_off = warpsum[0] + warpsum[1] + warpsum[2] + warpsum[3];
    __syncthreads();
    int i = bid * 512 + t;
    if (i < N) g_rowstart[i] += s_off;
    if (i == N) g_rowstart[N] = E;
}

__global__ void fill_kernel(const int* __restrict__ src,
                            const int* __restrict__ dst, int E) {
    int e = blockIdx.x * blockDim.x + threadIdx.x;
    if (e < E) {
        int d = dst[e];
        int pos = g_rowstart[d] + atomicAdd(&g_cursor[d], 1);
        g_csr[pos] = make_int2(src[e], e);
    }
}

// ---------------------------------------------------------------------------
// Gather aggregation -> bf16 hi/lo rows of [agg_h | agg_e]
// One 64-lane group per dst node, 4 nodes per 256-thr block (R11, measured best)
// edge_feat loaded evict-first (read-once stream; protect feat in L2).
// ---------------------------------------------------------------------------
__device__ __forceinline__ void split_store2(__nv_bfloat16* hi, __nv_bfloat16* lo,
                                             float a, float b) {
    __nv_bfloat16 ha = __float2bfloat16(a), hb = __float2bfloat16(b);
    __nv_bfloat16 la = __float2bfloat16(a - __bfloat162float(ha));
    __nv_bfloat16 lb = __float2bfloat16(b - __bfloat162float(hb));
    *(__nv_bfloat162*)hi = __nv_bfloat162(ha, hb);
    *(__nv_bfloat162*)lo = __nv_bfloat162(la, lb);
}

__global__ __launch_bounds__(256)
void agg_kernel(const float4* __restrict__ feat4,
                const float4* __restrict__ edge4, int N, int E) {
    int node = blockIdx.x * 4 + (threadIdx.x >> 6);
    int lane = threadIdx.x & 63;
    if (node >= N) return;
    int beg = g_rowstart[node];
    int end = g_rowstart[node + 1];

    float4 acc  = make_float4(0.f, 0.f, 0.f, 0.f);
    float4 acce = make_float4(0.f, 0.f, 0.f, 0.f);

    if (beg < end) {
        int2 nxt = __ldg(&g_csr[beg]);
        for (int i = beg; i < end; i++) {
            int2 cur = nxt;
            if (i + 1 < end) nxt = __ldg(&g_csr[i + 1]);
            float ns = g_norm_out[cur.x];
            float4 v = __ldg(feat4 + (size_t)cur.x * (FIN / 4) + lane);
            acc.x = fmaf(v.x, ns, acc.x);
            acc.y = fmaf(v.y, ns, acc.y);
            acc.z = fmaf(v.z, ns, acc.z);
            acc.w = fmaf(v.w, ns, acc.w);
            if (lane < FE / 4) {
                float4 ev = __ldcs(edge4 + (size_t)cur.y * (FE / 4) + lane);
                acce.x += ev.x; acce.y += ev.y; acce.z += ev.z; acce.w += ev.w;
            }
        }
    }
    __nv_bfloat16* rh = g_agg_hi + (size_t)node * FTOT;
    __nv_bfloat16* rl = g_agg_lo + (size_t)node * FTOT;
    split_store2(rh + lane * 4,     rl + lane * 4,     acc.x, acc.y);
    split_store2(rh + lane * 4 + 2, rl + lane * 4 + 2, acc.z, acc.w);
    if (lane < FE / 4) {
        split_store2(rh + FIN + lane * 4,     rl + FIN + lane * 4,     acce.x, acce.y);
        split_store2(rh + FIN + lane * 4 + 2, rl + FIN + lane * 4 + 2, acce.z, acce.w);
    }
}

// ---------------------------------------------------------------------------
// Tensor-core GEMM via mma.sync (R8/R11 version, measured best):
//   out[128-tile, 128-tile] = agg(hi,lo) [M,320] @ Wt(hi,lo)^T [256,320]
// CTA: 256 thr = 8 warps (2m x 4n); warp tile 64x32; K-chunks of 32.
// ---------------------------------------------------------------------------
#define KC 32
#define AST 40   // smem row stride (bf16 units): conflict-free frag loads

__device__ __forceinline__ void mma16816(float* c, const uint32_t* a, const uint32_t* b) {
    asm volatile("mma.sync.aligned.m16n8k16.row.col.f32.bf16.bf16.f32 "
        "{%0,%1,%2,%3}, {%4,%5,%6,%7}, {%8,%9}, {%0,%1,%2,%3};"
        : "+f"(c[0]), "+f"(c[1]), "+f"(c[2]), "+f"(c[3])
        : "r"(a[0]), "r"(a[1]), "r"(a[2]), "r"(a[3]), "r"(b[0]), "r"(b[1]));
}

__global__ __launch_bounds__(256)
void gemm_mma_kernel(const float* __restrict__ bias,
                     float* __restrict__ out, int M) {
    __shared__ __nv_bfloat16 Ah[128 * AST], Al[128 * AST];
    __shared__ __nv_bfloat16 Bh[128 * AST], Bl[128 * AST];

    int tid = threadIdx.x;
    int wid = tid >> 5, lid = tid & 31;
    int row0 = blockIdx.y * 128;
    int col0 = blockIdx.x * 128;
    int wm = (wid >> 2) * 64;      // warp m offset: 0/64
    int wn = (wid & 3) * 32;       // warp n offset: 0/32/64/96
    int qr = lid >> 2;             // 0..7
    int qc = (lid & 3) * 2;        // 0,2,4,6

    float acc[4][4][4];
#pragma unroll
    for (int mf = 0; mf < 4; mf++)
#pragma unroll
        for (int nf = 0; nf < 4; nf++)
#pragma unroll
            for (int q = 0; q < 4; q++) acc[mf][nf][q] = 0.f;

    int r_ = tid >> 2, u_ = tid & 3;
    const int NCH = FTOT / KC;   // 10

    uint4 pah[2], pal[2], pbh[2], pbl[2];
    uint4 z4 = make_uint4(0, 0, 0, 0);

#define LOAD_CHUNK(c)                                                          \
    {                                                                          \
        _Pragma("unroll")                                                      \
        for (int i = 0; i < 2; i++) {                                          \
            int r = r_ + i * 64;                                               \
            int rg = row0 + r;                                                 \
            size_t go = (size_t)rg * FTOT + (c) * KC + u_ * 8;                 \
            if (rg < M) {                                                      \
                pah[i] = *(const uint4*)(g_agg_hi + go);                       \
                pal[i] = *(const uint4*)(g_agg_lo + go);                       \
            } else { pah[i] = z4; pal[i] = z4; }                               \
            size_t gw = (size_t)(col0 + r) * FTOT + (c) * KC + u_ * 8;         \
            pbh[i] = *(const uint4*)(g_wt_hi + gw);                            \
            pbl[i] = *(const uint4*)(g_wt_lo + gw);                            \
        }                                                                      \
    }

    LOAD_CHUNK(0);

    for (int c = 0; c < NCH; c++) {
#pragma unroll
        for (int i = 0; i < 2; i++) {
            int r = r_ + i * 64;
            int so = r * AST + u_ * 8;
            *(uint4*)&Ah[so] = pah[i];
            *(uint4*)&Al[so] = pal[i];
            *(uint4*)&Bh[so] = pbh[i];
            *(uint4*)&Bl[so] = pbl[i];
        }
        __syncthreads();

        if (c + 1 < NCH) LOAD_CHUNK(c + 1);

#pragma unroll
        for (int ko = 0; ko < KC; ko += 16) {
            uint32_t bh[4][2], bl[4][2];
#pragma unroll
            for (int nf = 0; nf < 4; nf++) {
                int nrow = wn + nf * 8 + qr;
                bh[nf][0] = *(const uint32_t*)&Bh[nrow * AST + ko + qc];
                bh[nf][1] = *(const uint32_t*)&Bh[nrow * AST + ko + qc + 8];
                bl[nf][0] = *(const uint32_t*)&Bl[nrow * AST + ko + qc];
                bl[nf][1] = *(const uint32_t*)&Bl[nrow * AST + ko + qc + 8];
            }
#pragma unroll
            for (int mf = 0; mf < 4; mf++) {
                int mrow = wm + mf * 16 + qr;
                uint32_t ah[4], al[4];
                ah[0] = *(const uint32_t*)&Ah[mrow * AST + ko + qc];
                ah[1] = *(const uint32_t*)&Ah[(mrow + 8) * AST + ko + qc];
                ah[2] = *(const uint32_t*)&Ah[mrow * AST + ko + qc + 8];
                ah[3] = *(const uint32_t*)&Ah[(mrow + 8) * AST + ko + qc + 8];
                al[0] = *(const uint32_t*)&Al[mrow * AST + ko + qc];
                al[1] = *(const uint32_t*)&Al[(mrow + 8) * AST + ko + qc];
                al[2] = *(const uint32_t*)&Al[mrow * AST + ko + qc + 8];
                al[3] = *(const uint32_t*)&Al[(mrow + 8) * AST + ko + qc + 8];
#pragma unroll
                for (int nf = 0; nf < 4; nf++) {
                    mma16816(acc[mf][nf], ah, bh[nf]);   // Ah*Bh
                    mma16816(acc[mf][nf], ah, bl[nf]);   // Ah*Bl
                    mma16816(acc[mf][nf], al, bh[nf]);   // Al*Bh
                }
            }
        }
        __syncthreads();
    }

#pragma unroll
    for (int mf = 0; mf < 4; mf++) {
        int ra = row0 + wm + mf * 16 + qr;
        int rb = ra + 8;
        float na = (ra < M) ? g_norm_in[ra] : 0.f;
        float nb = (rb < M) ? g_norm_in[rb] : 0.f;
#pragma unroll
        for (int nf = 0; nf < 4; nf++) {
            int col = col0 + wn + nf * 8 + qc;
            float b0 = __ldg(bias + col), b1 = __ldg(bias + col + 1);
            if (ra < M) {
                float2 o;
                o.x = fmaxf(fmaf(acc[mf][nf][0], na, b0), 0.f);
                o.y = fmaxf(fmaf(acc[mf][nf][1], na, b1), 0.f);
                *(float2*)&out[(size_t)ra * FOUT + col] = o;
            }
            if (rb < M) {
                float2 o;
                o.x = fmaxf(fmaf(acc[mf][nf][2], nb, b0), 0.f);
                o.y = fmaxf(fmaf(acc[mf][nf][3], nb, b1), 0.f);
                *(float2*)&out[(size_t)rb * FOUT + col] = o;
            }
        }
    }
}

// ---------------------------------------------------------------------------
extern "C" void kernel_launch(void* const* d_in, const int* in_sizes, int n_in,
                              void* d_out, int out_size) {
    const float* feat      = (const float*)d_in[0];
    const float* edge_feat = (const float*)d_in[1];
    const float* weight    = (const float*)d_in[2];
    const float* bias      = (const float*)d_in[3];
    const int*   src       = (const int*)d_in[4];
    const int*   dst       = (const int*)d_in[5];
    float* out = (float*)d_out;

    int N = in_sizes[0] / FIN;   // 50000
    int E = in_sizes[4];         // 800000

    int scan_blocks = (N + 512) / 512;   // 98

    zero_kernel<<<(N + 255) / 256, 256>>>(N);
    deg_kernel<<<(E + 255) / 256, 256>>>(src, dst, E);
    scanA_kernel<<<scan_blocks, 512>>>(N);            // norms + cursor clear fused
    scanC_kernel<<<scan_blocks, 512>>>(N, E, scan_blocks);  // local bsum reduce
    fill_kernel<<<(E + 255) / 256, 256>>>(src, dst, E);
    wsplit_kernel<<<(FTOT * FOUT + 255) / 256, 256>>>(weight);

    agg_kernel<<<(N + 3) / 4, 256>>>((const float4*)feat, (const float4*)edge_feat, N, E);

    dim3 ggrid(FOUT / 128, (N + 127) / 128);
    gemm_mma_kernel<<<ggrid, 256>>>(bias, out, N);
}

// round 16
// speedup vs baseline: 1.1306x; 1.0598x over previous
#include <cuda_runtime.h>
#include <cuda_bf16.h>
#include <cstdint>

#define NODES_MAX 50000
#define EDGES_MAX 800000
#define FIN 256
#define FE  64
#define FTOT 320
#define FOUT 256

// ---------------------------------------------------------------------------
// Scratch (__device__ globals; allocation-free rule)
// ---------------------------------------------------------------------------
__device__ __nv_bfloat16 g_agg_hi[(size_t)NODES_MAX * FTOT];  // 32 MB
__device__ __nv_bfloat16 g_agg_lo[(size_t)NODES_MAX * FTOT];  // 32 MB
__device__ __nv_bfloat16 g_wt_hi[(size_t)FOUT * FTOT];        // W^T [N,K]
__device__ __nv_bfloat16 g_wt_lo[(size_t)FOUT * FTOT];
__device__ int   g_outd[NODES_MAX];
__device__ int   g_ind[NODES_MAX];
__device__ int   g_cursor[NODES_MAX];
__device__ float g_norm_out[NODES_MAX];
__device__ float g_norm_in[NODES_MAX];
__device__ int   g_rowstart[NODES_MAX + 1];
__device__ int   g_bsum[256];
__device__ int2  g_csr[EDGES_MAX];

// ---------------------------------------------------------------------------
__global__ void zero_kernel(int N) {
    int i = blockIdx.x * blockDim.x + threadIdx.x;
    if (i < N) { g_outd[i] = 0; g_ind[i] = 0; }
}

__global__ void deg_kernel(const int* __restrict__ src,
                           const int* __restrict__ dst, int E) {
    int e = blockIdx.x * blockDim.x + threadIdx.x;
    if (e < E) {
        atomicAdd(&g_outd[src[e]], 1);
        atomicAdd(&g_ind[dst[e]], 1);
    }
}

// W [320,256] row-major -> Wt [256,320] bf16 hi/lo
__global__ void wsplit_kernel(const float* __restrict__ W) {
    int idx = blockIdx.x * blockDim.x + threadIdx.x;
    if (idx < FTOT * FOUT) {
        int k = idx >> 8;      // /256
        int n = idx & 255;
        float w = W[idx];
        __nv_bfloat16 h = __float2bfloat16(w);
        __nv_bfloat16 l = __float2bfloat16(w - __bfloat162float(h));
        g_wt_hi[(size_t)n * FTOT + k] = h;
        g_wt_lo[(size_t)n * FTOT + k] = l;
    }
}

// ---- scanA: fused norm computation + cursor clear + block scan of g_ind ----
__global__ void scanA_kernel(int N) {
    __shared__ int sm[512];
    int t = threadIdx.x;
    int i = blockIdx.x * 512 + t;
    int v = 0;
    if (i < N) {
        int od = g_outd[i], id = g_ind[i];
        g_norm_out[i] = rsqrtf((float)max(od, 1));
        g_norm_in[i]  = rsqrtf((float)max(id, 1));
        g_cursor[i] = 0;
        v = id;
    }
    sm[t] = v;
    __syncthreads();
#pragma unroll
    for (int off = 1; off < 512; off <<= 1) {
        int x = (t >= off) ? sm[t - off] : 0;
        __syncthreads();
        sm[t] += x;
        __syncthreads();
    }
    if (i <= N) g_rowstart[i] = sm[t] - v;   // exclusive (within block)
    if (t == 511) g_bsum[blockIdx.x] = sm[511];
}

// scanC: each block reduces g_bsum[0..bid) locally
__global__ void scanC_kernel(int N, int E, int nblocks) {
    __shared__ int warpsum[4];
    __shared__ int s_off;
    int t = threadIdx.x;
    int bid = blockIdx.x;
    if (t < 128) {
        int v = (t < nblocks && t < bid) ? g_bsum[t] : 0;
#pragma unroll
        for (int o = 16; o > 0; o >>= 1) v += __shfl_down_sync(0xffffffffu, v, o);
        if ((t & 31) == 0) warpsum[t >> 5] = v;
    }
    __syncthreads();
    if (t == 0) s_off = warpsum[0] + warpsum[1] + warpsum[2] + warpsum[3];
    __syncthreads();
    int i = bid * 512 + t;
    if (i < N) g_rowstart[i] += s_off;
    if (i == N) g_rowstart[N] = E;
}

__global__ void fill_kernel(const int* __restrict__ src,
                            const int* __restrict__ dst, int E) {
    int e = blockIdx.x * blockDim.x + threadIdx.x;
    if (e < E) {
        int d = dst[e];
        int pos = g_rowstart[d] + atomicAdd(&g_cursor[d], 1);
        g_csr[pos] = make_int2(src[e], e);
    }
}

// ---------------------------------------------------------------------------
// Gather aggregation -> bf16 hi/lo rows of norm_in[d] * [agg_h | agg_e]
// (norm_in folded here: norm_in . (concat @ W) == (norm_in . concat) @ W)
// One 64-lane group per dst node, 4 nodes per 256-thr block (measured best).
// ---------------------------------------------------------------------------
__device__ __forceinline__ void split_store2(__nv_bfloat16* hi, __nv_bfloat16* lo,
                                             float a, float b) {
    __nv_bfloat16 ha = __float2bfloat16(a), hb = __float2bfloat16(b);
    __nv_bfloat16 la = __float2bfloat16(a - __bfloat162float(ha));
    __nv_bfloat16 lb = __float2bfloat16(b - __bfloat162float(hb));
    *(__nv_bfloat162*)hi = __nv_bfloat162(ha, hb);
    *(__nv_bfloat162*)lo = __nv_bfloat162(la, lb);
}

__global__ __launch_bounds__(256)
void agg_kernel(const float4* __restrict__ feat4,
                const float4* __restrict__ edge4, int N, int E) {
    int node = blockIdx.x * 4 + (threadIdx.x >> 6);
    int lane = threadIdx.x & 63;
    if (node >= N) return;
    int beg = g_rowstart[node];
    int end = g_rowstart[node + 1];

    float4 acc  = make_float4(0.f, 0.f, 0.f, 0.f);
    float4 acce = make_float4(0.f, 0.f, 0.f, 0.f);

    if (beg < end) {
        int2 nxt = __ldg(&g_csr[beg]);
        for (int i = beg; i < end; i++) {
            int2 cur = nxt;
            if (i + 1 < end) nxt = __ldg(&g_csr[i + 1]);
            float ns = g_norm_out[cur.x];
            float4 v = __ldg(feat4 + (size_t)cur.x * (FIN / 4) + lane);
            acc.x = fmaf(v.x, ns, acc.x);
            acc.y = fmaf(v.y, ns, acc.y);
            acc.z = fmaf(v.z, ns, acc.z);
            acc.w = fmaf(v.w, ns, acc.w);
            if (lane < FE / 4) {
                float4 ev = __ldcs(edge4 + (size_t)cur.y * (FE / 4) + lane);
                acce.x += ev.x; acce.y += ev.y; acce.z += ev.z; acce.w += ev.w;
            }
        }
    }
    float ni = g_norm_in[node];
    acc.x *= ni; acc.y *= ni; acc.z *= ni; acc.w *= ni;
    acce.x *= ni; acce.y *= ni; acce.z *= ni; acce.w *= ni;

    __nv_bfloat16* rh = g_agg_hi + (size_t)node * FTOT;
    __nv_bfloat16* rl = g_agg_lo + (size_t)node * FTOT;
    split_store2(rh + lane * 4,     rl + lane * 4,     acc.x, acc.y);
    split_store2(rh + lane * 4 + 2, rl + lane * 4 + 2, acc.z, acc.w);
    if (lane < FE / 4) {
        split_store2(rh + FIN + lane * 4,     rl + FIN + lane * 4,     acce.x, acce.y);
        split_store2(rh + FIN + lane * 4 + 2, rl + FIN + lane * 4 + 2, acce.z, acce.w);
    }
}

// ---------------------------------------------------------------------------
// Tensor-core GEMM, BN=256 (full width per CTA):
//   out[128-tile, 256] = agg(hi,lo) [M,320] @ Wt(hi,lo)^T [256,320]
// 512 thr = 16 warps (2m x 8n); warp tile 64x32 (unchanged inner loop);
// K-chunks of 32; epilogue = bias + relu (norm_in already folded into A).
// ---------------------------------------------------------------------------
#define KC 32
#define AST 40   // smem row stride (bf16 units): conflict-free frag loads
#define GEMM_SMEM ((128 * AST * 2 + 256 * AST * 2) * 2)   // 61440 bytes

__device__ __forceinline__ void mma16816(float* c, const uint32_t* a, const uint32_t* b) {
    asm volatile("mma.sync.aligned.m16n8k16.row.col.f32.bf16.bf16.f32 "
        "{%0,%1,%2,%3}, {%4,%5,%6,%7}, {%8,%9}, {%0,%1,%2,%3};"
        : "+f"(c[0]), "+f"(c[1]), "+f"(c[2]), "+f"(c[3])
        : "r"(a[0]), "r"(a[1]), "r"(a[2]), "r"(a[3]), "r"(b[0]), "r"(b[1]));
}

__global__ __launch_bounds__(512, 1)
void gemm_mma_kernel(const float* __restrict__ bias,
                     float* __restrict__ out, int M) {
    extern __shared__ __nv_bfloat16 smem[];
    __nv_bfloat16* Ah = smem;
    __nv_bfloat16* Al = Ah + 128 * AST;
    __nv_bfloat16* Bh = Al + 128 * AST;
    __nv_bfloat16* Bl = Bh + 256 * AST;

    int tid = threadIdx.x;
    int wid = tid >> 5, lid = tid & 31;
    int row0 = blockIdx.x * 128;
    int wm = (wid >> 3) * 64;      // warp m offset: 0/64
    int wn = (wid & 7) * 32;       // warp n offset: 0..224
    int qr = lid >> 2;             // 0..7
    int qc = (lid & 3) * 2;        // 0,2,4,6

    float acc[4][4][4];
#pragma unroll
    for (int mf = 0; mf < 4; mf++)
#pragma unroll
        for (int nf = 0; nf < 4; nf++)
#pragma unroll
            for (int q = 0; q < 4; q++) acc[mf][nf][q] = 0.f;

    int rA = tid >> 2, uA = tid & 3;            // A: 512 thr cover 128x32 hi+lo
    const int NCH = FTOT / KC;   // 10

    uint4 pah, pal, pbh[2], pbl[2];
    uint4 z4 = make_uint4(0, 0, 0, 0);

#define LOAD_CHUNK(c)                                                          \
    {                                                                          \
        int rg = row0 + rA;                                                    \
        size_t go = (size_t)rg * FTOT + (c) * KC + uA * 8;                     \
        if (rg < M) {                                                          \
            pah = *(const uint4*)(g_agg_hi + go);                              \
            pal = *(const uint4*)(g_agg_lo + go);                              \
        } else { pah = z4; pal = z4; }                                         \
        _Pragma("unroll")                                                      \
        for (int i = 0; i < 2; i++) {                                          \
            int idx = tid + i * 512;                                           \
            size_t gw = (size_t)(idx >> 2) * FTOT + (c) * KC + (idx & 3) * 8;  \
            pbh[i] = *(const uint4*)(g_wt_hi + gw);                            \
            pbl[i] = *(const uint4*)(g_wt_lo + gw);                            \
        }                                                                      \
    }

    LOAD_CHUNK(0);

    for (int c = 0; c < NCH; c++) {
        {
            int so = rA * AST + uA * 8;
            *(uint4*)&Ah[so] = pah;
            *(uint4*)&Al[so] = pal;
        }
#pragma unroll
        for (int i = 0; i < 2; i++) {
            int idx = tid + i * 512;
            int so = (idx >> 2) * AST + (idx & 3) * 8;
            *(uint4*)&Bh[so] = pbh[i];
            *(uint4*)&Bl[so] = pbl[i];
        }
        __syncthreads();

        if (c + 1 < NCH) LOAD_CHUNK(c + 1);

#pragma unroll
        for (int ko = 0; ko < KC; ko += 16) {
            uint32_t bh[4][2], bl[4][2];
#pragma unroll
            for (int nf = 0; nf < 4; nf++) {
                int nrow = wn + nf * 8 + qr;
                bh[nf][0] = *(const uint32_t*)&Bh[nrow * AST + ko + qc];
                bh[nf][1] = *(const uint32_t*)&Bh[nrow * AST + ko + qc + 8];
                bl[nf][0] = *(const uint32_t*)&Bl[nrow * AST + ko + qc];
                bl[nf][1] = *(const uint32_t*)&Bl[nrow * AST + ko + qc + 8];
            }
#pragma unroll
            for (int mf = 0; mf < 4; mf++) {
                int mrow = wm + mf * 16 + qr;
                uint32_t ah[4], al[4];
                ah[0] = *(const uint32_t*)&Ah[mrow * AST + ko + qc];
                ah[1] = *(const uint32_t*)&Ah[(mrow + 8) * AST + ko + qc];
                ah[2] = *(const uint32_t*)&Ah[mrow * AST + ko + qc + 8];
                ah[3] = *(const uint32_t*)&Ah[(mrow + 8) * AST + ko + qc + 8];
                al[0] = *(const uint32_t*)&Al[mrow * AST + ko + qc];
                al[1] = *(const uint32_t*)&Al[(mrow + 8) * AST + ko + qc];
                al[2] = *(const uint32_t*)&Al[mrow * AST + ko + qc + 8];
                al[3] = *(const uint32_t*)&Al[(mrow + 8) * AST + ko + qc + 8];
#pragma unroll
                for (int nf = 0; nf < 4; nf++) {
                    mma16816(acc[mf][nf], ah, bh[nf]);   // Ah*Bh
                    mma16816(acc[mf][nf], ah, bl[nf]);   // Ah*Bl
                    mma16816(acc[mf][nf], al, bh[nf]);   // Al*Bh
                }
            }
        }
        __syncthreads();
    }

#pragma unroll
    for (int mf = 0; mf < 4; mf++) {
        int ra = row0 + wm + mf * 16 + qr;
        int rb = ra + 8;
#pragma unroll
        for (int nf = 0; nf < 4; nf++) {
            int col = wn + nf * 8 + qc;
            float b0 = __ldg(bias + col), b1 = __ldg(bias + col + 1);
            if (ra < M) {
                float2 o;
                o.x = fmaxf(acc[mf][nf][0] + b0, 0.f);
                o.y = fmaxf(acc[mf][nf][1] + b1, 0.f);
                *(float2*)&out[(size_t)ra * FOUT + col] = o;
            }
            if (rb < M) {
                float2 o;
                o.x = fmaxf(acc[mf][nf][2] + b0, 0.f);
                o.y = fmaxf(acc[mf][nf][3] + b1, 0.f);
                *(float2*)&out[(size_t)rb * FOUT + col] = o;
            }
        }
    }
}

// ---------------------------------------------------------------------------
extern "C" void kernel_launch(void* const* d_in, const int* in_sizes, int n_in,
                              void* d_out, int out_size) {
    const float* feat      = (const float*)d_in[0];
    const float* edge_feat = (const float*)d_in[1];
    const float* weight    = (const float*)d_in[2];
    const float* bias      = (const float*)d_in[3];
    const int*   src       = (const int*)d_in[4];
    const int*   dst       = (const int*)d_in[5];
    float* out = (float*)d_out;

    int N = in_sizes[0] / FIN;   // 50000
    int E = in_sizes[4];         // 800000

    int scan_blocks = (N + 512) / 512;   // 98

    cudaFuncSetAttribute(gemm_mma_kernel,
                         cudaFuncAttributeMaxDynamicSharedMemorySize, GEMM_SMEM);

    zero_kernel<<<(N + 255) / 256, 256>>>(N);
    deg_kernel<<<(E + 255) / 256, 256>>>(src, dst, E);
    scanA_kernel<<<scan_blocks, 512>>>(N);                  // norms + cursor clear
    scanC_kernel<<<scan_blocks, 512>>>(N, E, scan_blocks);  // local bsum reduce
    fill_kernel<<<(E + 255) / 256, 256>>>(src, dst, E);
    wsplit_kernel<<<(FTOT * FOUT + 255) / 256, 256>>>(weight);

    agg_kernel<<<(N + 3) / 4, 256>>>((const float4*)feat, (const float4*)edge_feat, N, E);

    gemm_mma_kernel<<<(N + 127) / 128, 512, GEMM_SMEM>>>(bias, out, N);
}